// round 1
// baseline (speedup 1.0000x reference)
#include <cuda_runtime.h>
#include <cuda_bf16.h>
#include <float.h>

#define PP  64
#define NN  2048
#define M1  512
#define M2  128
#define KNB 32

// ---- output layout (float32, concatenated in reference return order) ----
#define OFF_XG     0            // [64,768]   = 49152
#define OFF_POSG   49152        // [64,3]     = 192
#define OFF_BATCHG 49344        // [64]       = 64
#define OFF_X2     49408        // [8192,384] = 3145728
#define OFF_Q2     3195136      // [8192,3]   = 24576
#define OFF_BATCH2 3219712      // [8192]     = 8192
#define OFF_VMIN   3227904      // [64,3]     = 192
#define OFF_DIFF   3228096      // [64]       = 64
// total 3228160

// ---- scratch (device globals; no allocation allowed) ----
__device__ float g_pn[PP * NN * 3];
__device__ float g_q1[PP * M1 * 3];
__device__ float g_q2[PP * M2 * 3];
__device__ int   g_idx1[PP * M1];
__device__ int   g_idx2[PP * M2];
__device__ int   g_nidx1[PP * M1 * KNB];
__device__ int   g_nidx2[PP * M2 * KNB];
__device__ float g_x1[PP * M1 * 128];

// Exact (non-contracted) squared distance, (dx^2 + dy^2) + dz^2 order.
__device__ __forceinline__ float d2_exact(float ax, float ay, float az,
                                          float bx, float by, float bz) {
    float dx = ax - bx, dy = ay - by, dz = az - bz;
    float s = __fmul_rn(dx, dx);
    s = __fadd_rn(s, __fmul_rn(dy, dy));
    s = __fadd_rn(s, __fmul_rn(dz, dz));
    return s;
}

// ---------------------------------------------------------------------------
// Init: zero xg, pos_g; write batch vectors (constant data).
// ---------------------------------------------------------------------------
__global__ void kinit(float* __restrict__ out) {
    int i = blockIdx.x * blockDim.x + threadIdx.x;
    if (i < 49152) out[OFF_XG + i] = 0.0f;
    if (i < 192)   out[OFF_POSG + i] = 0.0f;
    if (i < 64)    out[OFF_BATCHG + i] = (float)i;
    if (i < 8192)  out[OFF_BATCH2 + i] = (float)(i >> 7);
}

// ---------------------------------------------------------------------------
// Per-patch min/max, diff, normalize -> g_pn; write v_min, diff outputs.
// One block per patch.
// ---------------------------------------------------------------------------
__global__ void knorm(const float* __restrict__ pos, float* __restrict__ out) {
    __shared__ float sbuf[256];
    __shared__ float smn[3], smx[3];
    __shared__ float sdiff;
    int tid = threadIdx.x, p = blockIdx.x;
    const float* base = pos + (size_t)p * NN * 3;

    float mn[3] = { FLT_MAX,  FLT_MAX,  FLT_MAX};
    float mx[3] = {-FLT_MAX, -FLT_MAX, -FLT_MAX};
    for (int i = tid; i < NN; i += 256) {
        float a = base[i * 3 + 0], b = base[i * 3 + 1], c = base[i * 3 + 2];
        mn[0] = fminf(mn[0], a); mx[0] = fmaxf(mx[0], a);
        mn[1] = fminf(mn[1], b); mx[1] = fmaxf(mx[1], b);
        mn[2] = fminf(mn[2], c); mx[2] = fmaxf(mx[2], c);
    }
    for (int r = 0; r < 6; r++) {
        sbuf[tid] = (r < 3) ? mn[r] : mx[r - 3];
        __syncthreads();
        for (int s = 128; s > 0; s >>= 1) {
            if (tid < s) {
                sbuf[tid] = (r < 3) ? fminf(sbuf[tid], sbuf[tid + s])
                                    : fmaxf(sbuf[tid], sbuf[tid + s]);
            }
            __syncthreads();
        }
        if (tid == 0) { if (r < 3) smn[r] = sbuf[0]; else smx[r - 3] = sbuf[0]; }
        __syncthreads();
    }
    if (tid == 0) {
        float d = fmaxf(fmaxf(smx[0] - smn[0], smx[1] - smn[1]), smx[2] - smn[2]);
        sdiff = d;
        out[OFF_VMIN + p * 3 + 0] = smn[0];
        out[OFF_VMIN + p * 3 + 1] = smn[1];
        out[OFF_VMIN + p * 3 + 2] = smn[2];
        out[OFF_DIFF + p] = d;
    }
    __syncthreads();
    float dv = sdiff;
    for (int o = tid; o < NN * 3; o += 256) {
        int d = o % 3;
        g_pn[(size_t)p * NN * 3 + o] = __fdiv_rn(base[o] - smn[d], dv);
    }
}

// ---------------------------------------------------------------------------
// Farthest point sampling. One block per patch, 256 threads.
// argmax tie-break: first (lowest) index, matching jnp.argmax.
// ---------------------------------------------------------------------------
template <int NSRC, int M, int STAGE>
__global__ void kfps() {
    const float* pts = (STAGE == 1) ? g_pn : g_q1;
    int*   idxout    = (STAGE == 1) ? g_idx1 : g_idx2;
    float* qout      = (STAGE == 1) ? g_q1 : g_q2;

    __shared__ float spx[NSRC], spy[NSRC], spz[NSRC], sd[NSRC];
    __shared__ float rv[256];
    __shared__ int   ri[256];
    int tid = threadIdx.x, p = blockIdx.x;
    const float* base = pts + (size_t)p * NSRC * 3;

    for (int i = tid; i < NSRC; i += 256) {
        spx[i] = base[i * 3 + 0];
        spy[i] = base[i * 3 + 1];
        spz[i] = base[i * 3 + 2];
    }
    __syncthreads();
    float x0 = spx[0], y0 = spy[0], z0 = spz[0];
    for (int i = tid; i < NSRC; i += 256)
        sd[i] = d2_exact(spx[i], spy[i], spz[i], x0, y0, z0);
    if (tid == 0) {
        idxout[p * M] = 0;
        qout[(size_t)p * M * 3 + 0] = x0;
        qout[(size_t)p * M * 3 + 1] = y0;
        qout[(size_t)p * M * 3 + 2] = z0;
    }
    __syncthreads();

    for (int it = 1; it < M; it++) {
        float bv = -1.0f; int bi = 0x7fffffff;
        for (int i = tid; i < NSRC; i += 256) {
            float v = sd[i];
            if (v > bv) { bv = v; bi = i; }   // ascending scan -> earliest on tie
        }
        rv[tid] = bv; ri[tid] = bi;
        __syncthreads();
        for (int s = 128; s > 0; s >>= 1) {
            if (tid < s) {
                float ov = rv[tid + s]; int oi = ri[tid + s];
                if (ov > rv[tid] || (ov == rv[tid] && oi < ri[tid])) {
                    rv[tid] = ov; ri[tid] = oi;
                }
            }
            __syncthreads();
        }
        int j = ri[0];
        float xj = spx[j], yj = spy[j], zj = spz[j];
        if (tid == 0) {
            idxout[p * M + it] = j;
            qout[((size_t)p * M + it) * 3 + 0] = xj;
            qout[((size_t)p * M + it) * 3 + 1] = yj;
            qout[((size_t)p * M + it) * 3 + 2] = zj;
        }
        for (int i = tid; i < NSRC; i += 256) {
            float nd = d2_exact(spx[i], spy[i], spz[i], xj, yj, zj);
            if (nd < sd[i]) sd[i] = nd;
        }
        __syncthreads();
    }
}

// ---------------------------------------------------------------------------
// Radius neighbor selection: up to KNB nearest points with d2 <= r2.
// One block (128 thr) per center. Invalid slots = -1.
// ---------------------------------------------------------------------------
template <int NSRC, int M, int STAGE>
__global__ void kneigh() {
    const float* src = (STAGE == 1) ? g_pn : g_q1;
    const float* q   = (STAGE == 1) ? g_q1 : g_q2;
    int* nidx        = (STAGE == 1) ? g_nidx1 : g_nidx2;
    const float r2   = (STAGE == 1) ? (float)(0.15 * 0.15) : (float)(0.3 * 0.3);

    __shared__ float sd[NSRC];
    __shared__ float rv[128];
    __shared__ int   ri[128];
    int tid = threadIdx.x;
    int center = blockIdx.x;
    int p = center / M;
    float qx = q[center * 3 + 0], qy = q[center * 3 + 1], qz = q[center * 3 + 2];
    const float* base = src + (size_t)p * NSRC * 3;

    for (int i = tid; i < NSRC; i += 128) {
        float d2 = d2_exact(base[i * 3], base[i * 3 + 1], base[i * 3 + 2], qx, qy, qz);
        sd[i] = (d2 <= r2) ? d2 : FLT_MAX;
    }
    __syncthreads();

    for (int k = 0; k < KNB; k++) {
        float bv = FLT_MAX; int bi = 0x7fffffff;
        for (int i = tid; i < NSRC; i += 128) {
            float v = sd[i];
            if (v < bv) { bv = v; bi = i; }
        }
        rv[tid] = bv; ri[tid] = bi;
        __syncthreads();
        for (int s = 64; s > 0; s >>= 1) {
            if (tid < s) {
                float ov = rv[tid + s]; int oi = ri[tid + s];
                if (ov < rv[tid] || (ov == rv[tid] && oi < ri[tid])) {
                    rv[tid] = ov; ri[tid] = oi;
                }
            }
            __syncthreads();
        }
        if (tid == 0) {
            float bvv = rv[0]; int j = ri[0];
            nidx[center * KNB + k] = (bvv < FLT_MAX) ? j : -1;
            if (bvv < FLT_MAX) sd[j] = FLT_MAX;
        }
        __syncthreads();
    }
}

// ---------------------------------------------------------------------------
// Stage-1 MLP: feat[32,6] -> 64 -> 128, max over valid K.  8 centers/block.
// Weights staged in shared once per block.
// ---------------------------------------------------------------------------
__global__ __launch_bounds__(128) void kmlp1(
    const float* __restrict__ W1a, const float* __restrict__ b1a,
    const float* __restrict__ W1b, const float* __restrict__ b1b) {
    __shared__ float sWa[6 * 64];
    __shared__ float sba[64];
    __shared__ float sWb[64 * 128];
    __shared__ float sbb[128];
    __shared__ float sfeat[6 * 32];    // [f][k]
    __shared__ float sh1[64 * 32];     // [hidden][k]
    __shared__ int   sj[32];
    __shared__ float sq[3];
    int tid = threadIdx.x;

    for (int i = tid; i < 6 * 64; i += 128)  sWa[i] = W1a[i];
    if (tid < 64) sba[tid] = b1a[tid];
    for (int i = tid; i < 64 * 128; i += 128) sWb[i] = W1b[i];
    sbb[tid] = b1b[tid];

    for (int cc = 0; cc < 8; cc++) {
        __syncthreads();
        int center = blockIdx.x * 8 + cc;
        int p = center >> 9;               // M1 = 512
        if (tid < 32) sj[tid] = g_nidx1[center * KNB + tid];
        if (tid < 3)  sq[tid] = g_q1[center * 3 + tid];
        __syncthreads();

        for (int o = tid; o < 192; o += 128) {
            int k = o & 31, f = o >> 5;
            int j = sj[k];
            float v = 0.0f;
            if (j >= 0) {
                int d = (f < 3) ? f : (f - 3);
                float pj = g_pn[((size_t)p * NN + j) * 3 + d];
                v = (f < 3) ? pj : (pj - sq[d]);
            }
            sfeat[f * 32 + k] = v;
        }
        __syncthreads();

        for (int o = tid; o < 64 * 32; o += 128) {
            int k = o & 31, c = o >> 5;
            float acc = sba[c];
            #pragma unroll
            for (int f = 0; f < 6; f++) acc += sfeat[f * 32 + k] * sWa[f * 64 + c];
            sh1[c * 32 + k] = fmaxf(acc, 0.0f);
        }
        __syncthreads();

        {
            int c = tid;                    // 128 output channels
            float acc[32];
            #pragma unroll
            for (int k = 0; k < 32; k++) acc[k] = 0.0f;
            for (int i = 0; i < 64; i++) {
                float w = sWb[i * 128 + c];
                const float4* h4 = (const float4*)&sh1[i * 32];
                #pragma unroll
                for (int t = 0; t < 8; t++) {
                    float4 v = h4[t];
                    acc[4 * t + 0] += v.x * w;
                    acc[4 * t + 1] += v.y * w;
                    acc[4 * t + 2] += v.z * w;
                    acc[4 * t + 3] += v.w * w;
                }
            }
            float b = sbb[c];
            float m = -FLT_MAX;
            #pragma unroll
            for (int k = 0; k < 32; k++)
                if (sj[k] >= 0) m = fmaxf(m, fmaxf(acc[k] + b, 0.0f));
            g_x1[(size_t)center * 128 + c] = m;
        }
    }
}

// ---------------------------------------------------------------------------
// Stage-2 MLP: feat[32,131] -> 256 -> 384, max over valid K. 1 center/block.
// Neighbors split into 2 groups of 16 to fit static shared; max fuses groups.
// Weights streamed from L2 (__ldg), features/hidden in shared (broadcast).
// ---------------------------------------------------------------------------
__global__ __launch_bounds__(128) void kmlp2(
    const float* __restrict__ W2a, const float* __restrict__ b2a,
    const float* __restrict__ W2b, const float* __restrict__ b2b,
    float* __restrict__ out) {
    __shared__ float sfeat[131 * 16];   // [i][k]
    __shared__ float sh1[256 * 16];     // [i][k]
    __shared__ int   sj[32];
    __shared__ float sq[3];
    int tid = threadIdx.x;
    int center = blockIdx.x;
    int p = center >> 7;                 // M2 = 128
    if (tid < 32) sj[tid] = g_nidx2[center * KNB + tid];
    if (tid < 3) {
        float qv = g_q2[center * 3 + tid];
        sq[tid] = qv;
        out[OFF_Q2 + center * 3 + tid] = qv;
    }
    float vmax[3] = {-FLT_MAX, -FLT_MAX, -FLT_MAX};

    for (int g = 0; g < 2; g++) {
        __syncthreads();
        for (int o = tid; o < 131 * 16; o += 128) {
            int kk = o & 15, i = o >> 4;
            int j = sj[g * 16 + kk];
            float v = 0.0f;
            if (j >= 0) {
                if (i < 128) v = g_x1[((size_t)p * M1 + j) * 128 + i];
                else         v = g_q1[((size_t)p * M1 + j) * 3 + (i - 128)] - sq[i - 128];
            }
            sfeat[i * 16 + kk] = v;
        }
        __syncthreads();

        for (int cit = 0; cit < 2; cit++) {
            int c = tid + cit * 128;
            float acc[16];
            #pragma unroll
            for (int k = 0; k < 16; k++) acc[k] = 0.0f;
            #pragma unroll 4
            for (int i = 0; i < 131; i++) {
                float w = __ldg(&W2a[i * 256 + c]);
                const float4* f4 = (const float4*)&sfeat[i * 16];
                #pragma unroll
                for (int t = 0; t < 4; t++) {
                    float4 v = f4[t];
                    acc[4 * t + 0] += v.x * w;
                    acc[4 * t + 1] += v.y * w;
                    acc[4 * t + 2] += v.z * w;
                    acc[4 * t + 3] += v.w * w;
                }
            }
            float b = __ldg(&b2a[c]);
            float4* d4 = (float4*)&sh1[c * 16];
            #pragma unroll
            for (int t = 0; t < 4; t++) {
                float4 v;
                v.x = fmaxf(acc[4 * t + 0] + b, 0.0f);
                v.y = fmaxf(acc[4 * t + 1] + b, 0.0f);
                v.z = fmaxf(acc[4 * t + 2] + b, 0.0f);
                v.w = fmaxf(acc[4 * t + 3] + b, 0.0f);
                d4[t] = v;
            }
        }
        __syncthreads();

        for (int cit = 0; cit < 3; cit++) {
            int c = tid + cit * 128;
            float acc[16];
            #pragma unroll
            for (int k = 0; k < 16; k++) acc[k] = 0.0f;
            #pragma unroll 4
            for (int i = 0; i < 256; i++) {
                float w = __ldg(&W2b[i * 384 + c]);
                const float4* f4 = (const float4*)&sh1[i * 16];
                #pragma unroll
                for (int t = 0; t < 4; t++) {
                    float4 v = f4[t];
                    acc[4 * t + 0] += v.x * w;
                    acc[4 * t + 1] += v.y * w;
                    acc[4 * t + 2] += v.z * w;
                    acc[4 * t + 3] += v.w * w;
                }
            }
            float b = __ldg(&b2b[c]);
            float m = vmax[cit];
            #pragma unroll
            for (int k = 0; k < 16; k++)
                if (sj[g * 16 + k] >= 0) m = fmaxf(m, fmaxf(acc[k] + b, 0.0f));
            vmax[cit] = m;
        }
    }
    #pragma unroll
    for (int cit = 0; cit < 3; cit++)
        out[OFF_X2 + (size_t)center * 384 + tid + cit * 128] = vmax[cit];
}

// ---------------------------------------------------------------------------
// Stage-3 MLP: feat[387] -> 512 -> 768 per center, global max over M2 via
// atomicMax (relu outputs >= 0, int compare valid).  8 centers/block.
// ---------------------------------------------------------------------------
__global__ __launch_bounds__(128) void kmlp3(
    const float* __restrict__ W3a, const float* __restrict__ b3a,
    const float* __restrict__ W3b, const float* __restrict__ b3b,
    float* __restrict__ out) {
    __shared__ float sfeat[387 * 8];    // [i][cen]
    __shared__ float sh1[512 * 8];      // [i][cen]
    int tid = threadIdx.x;
    int base = blockIdx.x * 8;
    int p = base >> 7;                   // 8 | 128 -> whole block in one patch

    for (int o = tid; o < 387 * 8; o += 128) {
        int cen = o & 7, i = o >> 3;
        int center = base + cen;
        float v = (i < 384) ? out[OFF_X2 + (size_t)center * 384 + i]
                            : out[OFF_Q2 + center * 3 + (i - 384)];
        sfeat[i * 8 + cen] = v;
    }
    __syncthreads();

    for (int cit = 0; cit < 4; cit++) {
        int c = tid + cit * 128;
        float acc[8];
        #pragma unroll
        for (int k = 0; k < 8; k++) acc[k] = 0.0f;
        #pragma unroll 4
        for (int i = 0; i < 387; i++) {
            float w = __ldg(&W3a[i * 512 + c]);
            const float4* f4 = (const float4*)&sfeat[i * 8];
            float4 v0 = f4[0], v1 = f4[1];
            acc[0] += v0.x * w; acc[1] += v0.y * w; acc[2] += v0.z * w; acc[3] += v0.w * w;
            acc[4] += v1.x * w; acc[5] += v1.y * w; acc[6] += v1.z * w; acc[7] += v1.w * w;
        }
        float b = __ldg(&b3a[c]);
        float4* d4 = (float4*)&sh1[c * 8];
        float4 o0, o1;
        o0.x = fmaxf(acc[0] + b, 0.0f); o0.y = fmaxf(acc[1] + b, 0.0f);
        o0.z = fmaxf(acc[2] + b, 0.0f); o0.w = fmaxf(acc[3] + b, 0.0f);
        o1.x = fmaxf(acc[4] + b, 0.0f); o1.y = fmaxf(acc[5] + b, 0.0f);
        o1.z = fmaxf(acc[6] + b, 0.0f); o1.w = fmaxf(acc[7] + b, 0.0f);
        d4[0] = o0; d4[1] = o1;
    }
    __syncthreads();

    for (int cit = 0; cit < 6; cit++) {
        int c = tid + cit * 128;
        float acc[8];
        #pragma unroll
        for (int k = 0; k < 8; k++) acc[k] = 0.0f;
        #pragma unroll 4
        for (int i = 0; i < 512; i++) {
            float w = __ldg(&W3b[i * 768 + c]);
            const float4* f4 = (const float4*)&sh1[i * 8];
            float4 v0 = f4[0], v1 = f4[1];
            acc[0] += v0.x * w; acc[1] += v0.y * w; acc[2] += v0.z * w; acc[3] += v0.w * w;
            acc[4] += v1.x * w; acc[5] += v1.y * w; acc[6] += v1.z * w; acc[7] += v1.w * w;
        }
        float b = __ldg(&b3b[c]);
        float m = 0.0f;                   // relu outputs >= 0
        #pragma unroll
        for (int k = 0; k < 8; k++) m = fmaxf(m, fmaxf(acc[k] + b, 0.0f));
        atomicMax((int*)&out[OFF_XG + p * 768 + c], __float_as_int(m));
    }
}

// ---------------------------------------------------------------------------
extern "C" void kernel_launch(void* const* d_in, const int* in_sizes, int n_in,
                              void* d_out, int out_size) {
    const float* pos = (const float*)d_in[0];
    // d_in[1] = pi (int64), unused
    const float* W1a = (const float*)d_in[2];
    const float* b1a = (const float*)d_in[3];
    const float* W1b = (const float*)d_in[4];
    const float* b1b = (const float*)d_in[5];
    const float* W2a = (const float*)d_in[6];
    const float* b2a = (const float*)d_in[7];
    const float* W2b = (const float*)d_in[8];
    const float* b2b = (const float*)d_in[9];
    const float* W3a = (const float*)d_in[10];
    const float* b3a = (const float*)d_in[11];
    const float* W3b = (const float*)d_in[12];
    const float* b3b = (const float*)d_in[13];
    float* out = (float*)d_out;

    kinit<<<192, 256>>>(out);
    knorm<<<PP, 256>>>(pos, out);
    kfps<NN, M1, 1><<<PP, 256>>>();
    kneigh<NN, M1, 1><<<PP * M1, 128>>>();
    kmlp1<<<PP * M1 / 8, 128>>>(W1a, b1a, W1b, b1b);
    kfps<M1, M2, 2><<<PP, 256>>>();
    kneigh<M1, M2, 2><<<PP * M2, 128>>>();
    kmlp2<<<PP * M2, 128>>>(W2a, b2a, W2b, b2b, out);
    kmlp3<<<PP * M2 / 8, 128>>>(W3a, b3a, W3b, b3b, out);
}

// round 2
// speedup vs baseline: 2.0973x; 2.0973x over previous
#include <cuda_runtime.h>
#include <cuda_bf16.h>
#include <float.h>

#define PP  64
#define NN  2048
#define M1  512
#define M2  128
#define KNB 32

typedef unsigned long long u64;

// ---- output layout (float32, concatenated in reference return order) ----
#define OFF_XG     0            // [64,768]
#define OFF_POSG   49152        // [64,3]
#define OFF_BATCHG 49344        // [64]
#define OFF_X2     49408        // [8192,384]
#define OFF_Q2     3195136      // [8192,3]
#define OFF_BATCH2 3219712      // [8192]
#define OFF_VMIN   3227904      // [64,3]
#define OFF_DIFF   3228096      // [64]

// ---- scratch (device globals; no allocation allowed) ----
__device__ float g_pn[PP * NN * 3];
__device__ float g_q1[PP * M1 * 3];
__device__ float g_q2[PP * M2 * 3];
__device__ int   g_nidx1[PP * M1 * KNB];
__device__ int   g_nidx2[PP * M2 * KNB];
__device__ float g_x1[PP * M1 * 128];

// Exact (non-contracted) squared distance, (dx^2 + dy^2) + dz^2 order.
__device__ __forceinline__ float d2_exact(float ax, float ay, float az,
                                          float bx, float by, float bz) {
    float dx = ax - bx, dy = ay - by, dz = az - bz;
    float s = __fmul_rn(dx, dx);
    s = __fadd_rn(s, __fmul_rn(dy, dy));
    s = __fadd_rn(s, __fmul_rn(dz, dz));
    return s;
}

// ---- packed f32x2 helpers (Blackwell FFMA2) ----
__device__ __forceinline__ u64 fma2(u64 a, u64 b, u64 c) {
    u64 d;
    asm("fma.rn.f32x2 %0, %1, %2, %3;" : "=l"(d) : "l"(a), "l"(b), "l"(c));
    return d;
}
__device__ __forceinline__ u64 dup2(float w) {
    u64 r;
    asm("mov.b64 %0, {%1, %1};" : "=l"(r) : "f"(w));
    return r;
}
__device__ __forceinline__ float2 unpk(u64 v) {
    float2 f;
    asm("mov.b64 {%0, %1}, %2;" : "=f"(f.x), "=f"(f.y) : "l"(v));
    return f;
}

// ---------------------------------------------------------------------------
__global__ void kinit(float* __restrict__ out) {
    int i = blockIdx.x * blockDim.x + threadIdx.x;
    if (i < 49152) out[OFF_XG + i] = 0.0f;
    if (i < 192)   out[OFF_POSG + i] = 0.0f;
    if (i < 64)    out[OFF_BATCHG + i] = (float)i;
    if (i < 8192)  out[OFF_BATCH2 + i] = (float)(i >> 7);
}

// ---------------------------------------------------------------------------
__global__ void knorm(const float* __restrict__ pos, float* __restrict__ out) {
    __shared__ float sbuf[256];
    __shared__ float smn[3], smx[3];
    __shared__ float sdiff;
    int tid = threadIdx.x, p = blockIdx.x;
    const float* base = pos + (size_t)p * NN * 3;

    float mn[3] = { FLT_MAX,  FLT_MAX,  FLT_MAX};
    float mx[3] = {-FLT_MAX, -FLT_MAX, -FLT_MAX};
    for (int i = tid; i < NN; i += 256) {
        float a = base[i * 3 + 0], b = base[i * 3 + 1], c = base[i * 3 + 2];
        mn[0] = fminf(mn[0], a); mx[0] = fmaxf(mx[0], a);
        mn[1] = fminf(mn[1], b); mx[1] = fmaxf(mx[1], b);
        mn[2] = fminf(mn[2], c); mx[2] = fmaxf(mx[2], c);
    }
    for (int r = 0; r < 6; r++) {
        sbuf[tid] = (r < 3) ? mn[r] : mx[r - 3];
        __syncthreads();
        for (int s = 128; s > 0; s >>= 1) {
            if (tid < s) {
                sbuf[tid] = (r < 3) ? fminf(sbuf[tid], sbuf[tid + s])
                                    : fmaxf(sbuf[tid], sbuf[tid + s]);
            }
            __syncthreads();
        }
        if (tid == 0) { if (r < 3) smn[r] = sbuf[0]; else smx[r - 3] = sbuf[0]; }
        __syncthreads();
    }
    if (tid == 0) {
        float d = fmaxf(fmaxf(smx[0] - smn[0], smx[1] - smn[1]), smx[2] - smn[2]);
        sdiff = d;
        out[OFF_VMIN + p * 3 + 0] = smn[0];
        out[OFF_VMIN + p * 3 + 1] = smn[1];
        out[OFF_VMIN + p * 3 + 2] = smn[2];
        out[OFF_DIFF + p] = d;
    }
    __syncthreads();
    float dv = sdiff;
    for (int o = tid; o < NN * 3; o += 256) {
        int d = o % 3;
        g_pn[(size_t)p * NN * 3 + o] = __fdiv_rn(base[o] - smn[d], dv);
    }
}

// ---------------------------------------------------------------------------
// FPS: fused update+argmax, 1 syncthreads/iter (parity-buffered cross-warp).
// key = (d2_bits << 32) | ~idx  -> max == max d2, tie -> lowest idx.
// ---------------------------------------------------------------------------
template <int NSRC, int M, int STAGE>
__global__ __launch_bounds__(256) void kfps() {
    const float* pts = (STAGE == 1) ? g_pn : g_q1;
    float* qout      = (STAGE == 1) ? g_q1 : g_q2;
    const int PT = NSRC / 256;

    __shared__ float sx[NSRC], sy[NSRC], sz[NSRC];
    __shared__ u64 wred[2][8];
    int tid = threadIdx.x, p = blockIdx.x;
    int lane = tid & 31, wid = tid >> 5;
    const float* base = pts + (size_t)p * NSRC * 3;

    float px[PT], py[PT], pz[PT], dd[PT];
    #pragma unroll
    for (int t = 0; t < PT; t++) {
        int i = tid + t * 256;
        float a = base[i * 3 + 0], b = base[i * 3 + 1], c = base[i * 3 + 2];
        sx[i] = a; sy[i] = b; sz[i] = c;
        px[t] = a; py[t] = b; pz[t] = c;
        dd[t] = FLT_MAX;
    }
    __syncthreads();
    float cx = sx[0], cy = sy[0], cz = sz[0];
    if (tid == 0) {
        qout[(size_t)p * M * 3 + 0] = cx;
        qout[(size_t)p * M * 3 + 1] = cy;
        qout[(size_t)p * M * 3 + 2] = cz;
    }

    for (int it = 1; it < M; it++) {
        u64 best = 0;
        #pragma unroll
        for (int t = 0; t < PT; t++) {
            float nd = d2_exact(px[t], py[t], pz[t], cx, cy, cz);
            dd[t] = fminf(dd[t], nd);
            unsigned idx = (unsigned)(tid + t * 256);
            u64 key = ((u64)__float_as_uint(dd[t]) << 32) | (u64)(~idx);
            best = (key > best) ? key : best;
        }
        #pragma unroll
        for (int off = 16; off > 0; off >>= 1) {
            u64 o = __shfl_xor_sync(0xffffffffu, best, off);
            best = (o > best) ? o : best;
        }
        if (lane == 0) wred[it & 1][wid] = best;
        __syncthreads();
        u64 m = wred[it & 1][0];
        #pragma unroll
        for (int w = 1; w < 8; w++) {
            u64 o = wred[it & 1][w];
            m = (o > m) ? o : m;
        }
        unsigned j = ~(unsigned)(m & 0xFFFFFFFFu);
        cx = sx[j]; cy = sy[j]; cz = sz[j];
        if (tid == 0) {
            qout[((size_t)p * M + it) * 3 + 0] = cx;
            qout[((size_t)p * M + it) * 3 + 1] = cy;
            qout[((size_t)p * M + it) * 3 + 2] = cz;
        }
    }
}

// ---------------------------------------------------------------------------
// Radius neighbors: warp-autonomous candidate collection + small selection.
// 256 threads = 8 warps, 2 groups of 8 centers per block (16 centers/block).
// key = (d2_bits << 32) | idx  -> min == min d2, tie -> lowest idx.
// ---------------------------------------------------------------------------
template <int NSRC, int M, int STAGE, int CAP>
__global__ __launch_bounds__(256) void kneigh() {
    const float* src  = (STAGE == 1) ? g_pn : g_q1;
    const float* qsrc = (STAGE == 1) ? g_q1 : g_q2;
    int* nidx         = (STAGE == 1) ? g_nidx1 : g_nidx2;
    const float r2    = (STAGE == 1) ? (float)(0.15 * 0.15) : (float)(0.3 * 0.3);

    extern __shared__ __align__(16) char dynbuf[];
    float* sx  = (float*)dynbuf;
    float* sy  = sx + NSRC;
    float* sz  = sy + NSRC;
    u64*  cand = (u64*)(sz + NSRC);        // [8][CAP]
    __shared__ int cnt[8];

    int tid = threadIdx.x;
    int lane = tid & 31, w = tid >> 5;
    int tilesPerPatch = M / 16;
    int p    = blockIdx.x / tilesPerPatch;
    int tile = blockIdx.x % tilesPerPatch;
    const float* base = src + (size_t)p * NSRC * 3;

    for (int i = tid; i < NSRC; i += 256) {
        sx[i] = base[i * 3 + 0];
        sy[i] = base[i * 3 + 1];
        sz[i] = base[i * 3 + 2];
    }
    __syncthreads();

    u64* mycand = cand + (size_t)w * CAP;

    for (int g = 0; g < 2; g++) {
        int center = p * M + tile * 16 + g * 8 + w;
        float qx = qsrc[center * 3 + 0];
        float qy = qsrc[center * 3 + 1];
        float qz = qsrc[center * 3 + 2];
        if (lane == 0) cnt[w] = 0;
        __syncwarp();

        for (int i = lane; i < NSRC; i += 32) {
            float d2 = d2_exact(sx[i], sy[i], sz[i], qx, qy, qz);
            if (d2 <= r2) {
                int pos = atomicAdd(&cnt[w], 1);
                if (pos < CAP)
                    mycand[pos] = ((u64)__float_as_uint(d2) << 32) | (unsigned)i;
            }
        }
        __syncwarp();
        int C = cnt[w];
        C = (C < CAP) ? C : CAP;

        if (C <= 32) {
            int v = (lane < C) ? (int)(unsigned)(mycand[lane] & 0xFFFFFFFFu) : -1;
            nidx[center * KNB + lane] = v;
        } else {
            for (int k = 0; k < KNB; k++) {
                u64 bv = 0xFFFFFFFFFFFFFFFFull;
                for (int i = lane; i < C; i += 32) {
                    u64 v = mycand[i];
                    bv = (v < bv) ? v : bv;
                }
                #pragma unroll
                for (int off = 16; off > 0; off >>= 1) {
                    u64 o = __shfl_xor_sync(0xffffffffu, bv, off);
                    bv = (o < bv) ? o : bv;
                }
                if (lane == 0)
                    nidx[center * KNB + k] = (int)(unsigned)(bv & 0xFFFFFFFFu);
                for (int i = lane; i < C; i += 32)
                    if (mycand[i] == bv) mycand[i] = 0xFFFFFFFFFFFFFFFFull;
                __syncwarp();
            }
        }
        __syncwarp();
    }
}

// ---------------------------------------------------------------------------
// Stage-1 MLP: feat[32,6] -> 64 -> 128, max over valid K.  8 centers/block.
// Layer-2 uses packed f32x2 FMA.
// ---------------------------------------------------------------------------
__global__ __launch_bounds__(128) void kmlp1(
    const float* __restrict__ W1a, const float* __restrict__ b1a,
    const float* __restrict__ W1b, const float* __restrict__ b1b) {
    __shared__ __align__(16) float sWa[6 * 64];
    __shared__ float sba[64];
    __shared__ __align__(16) float sWb[64 * 128];
    __shared__ float sbb[128];
    __shared__ __align__(16) float sfeat[6 * 32];    // [f][k]
    __shared__ __align__(16) float sh1[64 * 32];     // [hidden][k]
    __shared__ int   sj[32];
    __shared__ float sq[3];
    int tid = threadIdx.x;

    for (int i = tid; i < 6 * 64; i += 128)  sWa[i] = W1a[i];
    if (tid < 64) sba[tid] = b1a[tid];
    for (int i = tid; i < 64 * 128; i += 128) sWb[i] = W1b[i];
    sbb[tid] = b1b[tid];

    for (int cc = 0; cc < 8; cc++) {
        __syncthreads();
        int center = blockIdx.x * 8 + cc;
        int p = center >> 9;
        if (tid < 32) sj[tid] = g_nidx1[center * KNB + tid];
        if (tid < 3)  sq[tid] = g_q1[center * 3 + tid];
        __syncthreads();

        for (int o = tid; o < 192; o += 128) {
            int k = o & 31, f = o >> 5;
            int j = sj[k];
            float v = 0.0f;
            if (j >= 0) {
                int d = (f < 3) ? f : (f - 3);
                float pj = g_pn[((size_t)p * NN + j) * 3 + d];
                v = (f < 3) ? pj : (pj - sq[d]);
            }
            sfeat[f * 32 + k] = v;
        }
        __syncthreads();

        for (int o = tid; o < 64 * 32; o += 128) {
            int k = o & 31, c = o >> 5;
            float acc = sba[c];
            #pragma unroll
            for (int f = 0; f < 6; f++) acc += sfeat[f * 32 + k] * sWa[f * 64 + c];
            sh1[c * 32 + k] = fmaxf(acc, 0.0f);
        }
        __syncthreads();

        {
            int c = tid;
            u64 acc[16];
            #pragma unroll
            for (int t = 0; t < 16; t++) acc[t] = 0ull;
            #pragma unroll 4
            for (int i = 0; i < 64; i++) {
                u64 wp = dup2(sWb[i * 128 + c]);
                const ulonglong2* h2 = (const ulonglong2*)&sh1[i * 32];
                #pragma unroll
                for (int t = 0; t < 8; t++) {
                    ulonglong2 v = h2[t];
                    acc[2 * t + 0] = fma2(v.x, wp, acc[2 * t + 0]);
                    acc[2 * t + 1] = fma2(v.y, wp, acc[2 * t + 1]);
                }
            }
            float b = sbb[c];
            float m = -FLT_MAX;
            #pragma unroll
            for (int t = 0; t < 16; t++) {
                float2 f = unpk(acc[t]);
                if (sj[2 * t + 0] >= 0) m = fmaxf(m, fmaxf(f.x + b, 0.0f));
                if (sj[2 * t + 1] >= 0) m = fmaxf(m, fmaxf(f.y + b, 0.0f));
            }
            g_x1[(size_t)center * 128 + c] = m;
        }
    }
}

// ---------------------------------------------------------------------------
// Stage-2 MLP: feat[32,131] -> 256 -> 384, max over valid K. 1 center/block.
// All 32 neighbors at once; packed f32x2 FMA; dynamic smem.
// ---------------------------------------------------------------------------
__global__ __launch_bounds__(128) void kmlp2(
    const float* __restrict__ W2a, const float* __restrict__ b2a,
    const float* __restrict__ W2b, const float* __restrict__ b2b,
    float* __restrict__ out) {
    extern __shared__ __align__(16) char smem2[];
    float* sfeat = (float*)smem2;          // [131][32]
    float* sh1   = sfeat + 131 * 32;       // [256][32]
    __shared__ int   sj[32];
    __shared__ float sq[3];
    int tid = threadIdx.x;
    int center = blockIdx.x;
    int p = center >> 7;
    if (tid < 32) sj[tid] = g_nidx2[center * KNB + tid];
    if (tid < 3) {
        float qv = g_q2[center * 3 + tid];
        sq[tid] = qv;
        out[OFF_Q2 + center * 3 + tid] = qv;
    }
    __syncthreads();

    for (int o = tid; o < 131 * 32; o += 128) {
        int k = o & 31, i = o >> 5;
        int j = sj[k];
        float v = 0.0f;
        if (j >= 0) {
            if (i < 128) v = g_x1[((size_t)p * M1 + j) * 128 + i];
            else         v = g_q1[((size_t)p * M1 + j) * 3 + (i - 128)] - sq[i - 128];
        }
        sfeat[i * 32 + k] = v;
    }
    __syncthreads();

    #pragma unroll
    for (int cit = 0; cit < 2; cit++) {
        int c = tid + cit * 128;
        u64 acc[16];
        #pragma unroll
        for (int t = 0; t < 16; t++) acc[t] = 0ull;
        #pragma unroll 4
        for (int i = 0; i < 131; i++) {
            u64 wp = dup2(__ldg(&W2a[i * 256 + c]));
            const ulonglong2* f2 = (const ulonglong2*)&sfeat[i * 32];
            #pragma unroll
            for (int t = 0; t < 8; t++) {
                ulonglong2 v = f2[t];
                acc[2 * t + 0] = fma2(v.x, wp, acc[2 * t + 0]);
                acc[2 * t + 1] = fma2(v.y, wp, acc[2 * t + 1]);
            }
        }
        float b = __ldg(&b2a[c]);
        float2* dst = (float2*)&sh1[c * 32];
        #pragma unroll
        for (int t = 0; t < 16; t++) {
            float2 f = unpk(acc[t]);
            dst[t] = make_float2(fmaxf(f.x + b, 0.0f), fmaxf(f.y + b, 0.0f));
        }
    }
    __syncthreads();

    #pragma unroll
    for (int cit = 0; cit < 3; cit++) {
        int c = tid + cit * 128;
        u64 acc[16];
        #pragma unroll
        for (int t = 0; t < 16; t++) acc[t] = 0ull;
        #pragma unroll 4
        for (int i = 0; i < 256; i++) {
            u64 wp = dup2(__ldg(&W2b[i * 384 + c]));
            const ulonglong2* f2 = (const ulonglong2*)&sh1[i * 32];
            #pragma unroll
            for (int t = 0; t < 8; t++) {
                ulonglong2 v = f2[t];
                acc[2 * t + 0] = fma2(v.x, wp, acc[2 * t + 0]);
                acc[2 * t + 1] = fma2(v.y, wp, acc[2 * t + 1]);
            }
        }
        float b = __ldg(&b2b[c]);
        float m = -FLT_MAX;
        #pragma unroll
        for (int t = 0; t < 16; t++) {
            float2 f = unpk(acc[t]);
            if (sj[2 * t + 0] >= 0) m = fmaxf(m, fmaxf(f.x + b, 0.0f));
            if (sj[2 * t + 1] >= 0) m = fmaxf(m, fmaxf(f.y + b, 0.0f));
        }
        out[OFF_X2 + (size_t)center * 384 + c] = m;
    }
}

// ---------------------------------------------------------------------------
// Stage-3 MLP: feat[387] -> 512 -> 768 per center; 16 centers/block (one
// patch-slice), local max over the 16 then one atomicMax per channel.
// ---------------------------------------------------------------------------
__global__ __launch_bounds__(128) void kmlp3(
    const float* __restrict__ W3a, const float* __restrict__ b3a,
    const float* __restrict__ W3b, const float* __restrict__ b3b,
    float* __restrict__ out) {
    extern __shared__ __align__(16) char smem3[];
    float* sfeat = (float*)smem3;          // [387][16]
    float* sh1   = sfeat + 387 * 16;       // [512][16]
    int tid = threadIdx.x;
    int base = blockIdx.x * 16;
    int p = base >> 7;

    for (int o = tid; o < 387 * 16; o += 128) {
        int cen = o & 15, i = o >> 4;
        int center = base + cen;
        float v = (i < 384) ? out[OFF_X2 + (size_t)center * 384 + i]
                            : out[OFF_Q2 + center * 3 + (i - 384)];
        sfeat[i * 16 + cen] = v;
    }
    __syncthreads();

    #pragma unroll
    for (int cit = 0; cit < 4; cit++) {
        int c = tid + cit * 128;
        u64 acc[8];
        #pragma unroll
        for (int t = 0; t < 8; t++) acc[t] = 0ull;
        #pragma unroll 4
        for (int i = 0; i < 387; i++) {
            u64 wp = dup2(__ldg(&W3a[i * 512 + c]));
            const ulonglong2* f2 = (const ulonglong2*)&sfeat[i * 16];
            #pragma unroll
            for (int t = 0; t < 4; t++) {
                ulonglong2 v = f2[t];
                acc[2 * t + 0] = fma2(v.x, wp, acc[2 * t + 0]);
                acc[2 * t + 1] = fma2(v.y, wp, acc[2 * t + 1]);
            }
        }
        float b = __ldg(&b3a[c]);
        float2* dst = (float2*)&sh1[c * 16];
        #pragma unroll
        for (int t = 0; t < 8; t++) {
            float2 f = unpk(acc[t]);
            dst[t] = make_float2(fmaxf(f.x + b, 0.0f), fmaxf(f.y + b, 0.0f));
        }
    }
    __syncthreads();

    #pragma unroll
    for (int cit = 0; cit < 6; cit++) {
        int c = tid + cit * 128;
        u64 acc[8];
        #pragma unroll
        for (int t = 0; t < 8; t++) acc[t] = 0ull;
        #pragma unroll 4
        for (int i = 0; i < 512; i++) {
            u64 wp = dup2(__ldg(&W3b[i * 768 + c]));
            const ulonglong2* f2 = (const ulonglong2*)&sh1[i * 16];
            #pragma unroll
            for (int t = 0; t < 4; t++) {
                ulonglong2 v = f2[t];
                acc[2 * t + 0] = fma2(v.x, wp, acc[2 * t + 0]);
                acc[2 * t + 1] = fma2(v.y, wp, acc[2 * t + 1]);
            }
        }
        float b = __ldg(&b3b[c]);
        float m = 0.0f;   // relu outputs >= 0
        #pragma unroll
        for (int t = 0; t < 8; t++) {
            float2 f = unpk(acc[t]);
            m = fmaxf(m, fmaxf(f.x + b, 0.0f));
            m = fmaxf(m, fmaxf(f.y + b, 0.0f));
        }
        atomicMax((int*)&out[OFF_XG + p * 768 + c], __float_as_int(m));
    }
}

// ---------------------------------------------------------------------------
extern "C" void kernel_launch(void* const* d_in, const int* in_sizes, int n_in,
                              void* d_out, int out_size) {
    const float* pos = (const float*)d_in[0];
    const float* W1a = (const float*)d_in[2];
    const float* b1a = (const float*)d_in[3];
    const float* W1b = (const float*)d_in[4];
    const float* b1b = (const float*)d_in[5];
    const float* W2a = (const float*)d_in[6];
    const float* b2a = (const float*)d_in[7];
    const float* W2b = (const float*)d_in[8];
    const float* b2b = (const float*)d_in[9];
    const float* W3a = (const float*)d_in[10];
    const float* b3a = (const float*)d_in[11];
    const float* W3b = (const float*)d_in[12];
    const float* b3b = (const float*)d_in[13];
    float* out = (float*)d_out;

    const int NEIGH1_SMEM = 3 * NN * 4 + 8 * 1024 * 8;   // 90112
    const int NEIGH2_SMEM = 3 * M1 * 4 + 8 * 512 * 8;    // 38912
    const int MLP2_SMEM   = (131 * 32 + 256 * 32) * 4;   // 49536
    const int MLP3_SMEM   = (387 * 16 + 512 * 16) * 4;   // 57536
    cudaFuncSetAttribute(kneigh<NN, M1, 1, 1024>,
                         cudaFuncAttributeMaxDynamicSharedMemorySize, NEIGH1_SMEM);
    cudaFuncSetAttribute(kneigh<M1, M2, 2, 512>,
                         cudaFuncAttributeMaxDynamicSharedMemorySize, NEIGH2_SMEM);
    cudaFuncSetAttribute(kmlp2,
                         cudaFuncAttributeMaxDynamicSharedMemorySize, MLP2_SMEM);
    cudaFuncSetAttribute(kmlp3,
                         cudaFuncAttributeMaxDynamicSharedMemorySize, MLP3_SMEM);

    kinit<<<192, 256>>>(out);
    knorm<<<PP, 256>>>(pos, out);
    kfps<NN, M1, 1><<<PP, 256>>>();
    kneigh<NN, M1, 1, 1024><<<PP * M1 / 16, 256, NEIGH1_SMEM>>>();
    kmlp1<<<PP * M1 / 8, 128>>>(W1a, b1a, W1b, b1b);
    kfps<M1, M2, 2><<<PP, 256>>>();
    kneigh<M1, M2, 2, 512><<<PP * M2 / 16, 256, NEIGH2_SMEM>>>();
    kmlp2<<<PP * M2, 128, MLP2_SMEM>>>(W2a, b2a, W2b, b2b, out);
    kmlp3<<<PP * M2 / 16, 128, MLP3_SMEM>>>(W3a, b3a, W3b, b3b, out);
}